// round 4
// baseline (speedup 1.0000x reference)
#include <cuda_runtime.h>
#include <cuda_bf16.h>
#include <math.h>

// Problem constants
#define BATCH   2
#define SEQ     2048
#define HID     2048
#define HEADS   16
#define HD      128
#define MROWS   (BATCH * SEQ)          // 4096
#define MSZ     ((size_t)MROWS * HID)  // 4096*2048 elements

// Scratch buffers (device globals: allocation-free per harness rules)
__device__ float g_Q[MSZ];
__device__ float g_K[MSZ];
__device__ float g_V[MSZ];
__device__ float g_A[MSZ];

// ---------------------------------------------------------------------------
// GEMM: C[M,N] = A[M,K] @ W[N,K]^T + bias[N]
// A row-major [M,K], W row-major [N,K] (torch Linear convention).
// 128x128 block, BK=8, 8x8 per-thread tile, 256 threads.
// Register-staged prefetch of the next K-tile overlaps LDG with FFMA.
// ---------------------------------------------------------------------------
#define BM 128
#define BN 128
#define BK 8
#define TM 8
#define TN 8

__global__ __launch_bounds__(256) void gemm_bias_nt(
    const float* __restrict__ A, const float* __restrict__ W,
    const float* __restrict__ bias, float* __restrict__ C,
    int M, int N, int K)
{
    __shared__ float As[BK][BM];
    __shared__ float Bs[BK][BN];

    const int tid = threadIdx.x;
    const int tx = tid & 15;       // 0..15 -> N direction
    const int ty = tid >> 4;       // 0..15 -> M direction
    const int row0 = blockIdx.y * BM;
    const int col0 = blockIdx.x * BN;

    // Load mapping: each thread loads one float4 per matrix per K-tile.
    const int lr = tid >> 1;            // 0..127
    const int lk = (tid & 1) * 4;       // 0 or 4

    const float* Aptr = A + (size_t)(row0 + lr) * K + lk;
    const float* Wptr = W + (size_t)(col0 + lr) * K + lk;

    float acc[TM][TN];
    #pragma unroll
    for (int i = 0; i < TM; ++i)
        #pragma unroll
        for (int j = 0; j < TN; ++j)
            acc[i][j] = 0.0f;

    // Prologue: load first K-tile into registers
    float4 av = *reinterpret_cast<const float4*>(Aptr);
    float4 wv = *reinterpret_cast<const float4*>(Wptr);

    for (int k0 = 0; k0 < K; k0 += BK) {
        As[lk + 0][lr] = av.x; As[lk + 1][lr] = av.y;
        As[lk + 2][lr] = av.z; As[lk + 3][lr] = av.w;
        Bs[lk + 0][lr] = wv.x; Bs[lk + 1][lr] = wv.y;
        Bs[lk + 2][lr] = wv.z; Bs[lk + 3][lr] = wv.w;
        __syncthreads();

        // Prefetch next K-tile (overlaps with the FFMA block below)
        if (k0 + BK < K) {
            av = *reinterpret_cast<const float4*>(Aptr + k0 + BK);
            wv = *reinterpret_cast<const float4*>(Wptr + k0 + BK);
        }

        #pragma unroll
        for (int k = 0; k < BK; ++k) {
            float a[TM], b[TN];
            #pragma unroll
            for (int i = 0; i < TM; ++i) a[i] = As[k][ty * TM + i];
            #pragma unroll
            for (int j = 0; j < TN; ++j) b[j] = Bs[k][tx * TN + j];
            #pragma unroll
            for (int i = 0; i < TM; ++i)
                #pragma unroll
                for (int j = 0; j < TN; ++j)
                    acc[i][j] += a[i] * b[j];
        }
        __syncthreads();
    }

    #pragma unroll
    for (int i = 0; i < TM; ++i) {
        int r = row0 + ty * TM + i;
        #pragma unroll
        for (int j = 0; j < TN; j += 4) {
            int c = col0 + tx * TN + j;
            float4 o;
            o.x = acc[i][j + 0] + bias[c + 0];
            o.y = acc[i][j + 1] + bias[c + 1];
            o.z = acc[i][j + 2] + bias[c + 2];
            o.w = acc[i][j + 3] + bias[c + 3];
            *reinterpret_cast<float4*>(C + (size_t)r * N + c) = o;
        }
    }
}

// ---------------------------------------------------------------------------
// Flash attention (fp32, no mask). One block per (batch*head, q-tile of 64).
// Q/K/V laid out as [B*S, HID] with head h occupying cols [h*HD, (h+1)*HD).
// 256 threads: tx=tid%16, ty=tid/16.
//   Scores S (64x64): thread owns rows ty*4+i, cols tx*4+j.
//   Output O (64x128): thread owns rows ty*4+i, cols tx*8+j.
// ---------------------------------------------------------------------------
#define BQ  64
#define BKV 64
#define QK_PAD 1   // row stride HD+1 = 129 (odd -> 2-way max conflicts)
#define V_PAD  4   // row stride HD+4 = 132 (float4-aligned)
#define P_PAD  4

#define QK_STR (HD + QK_PAD)   // 129
#define V_STR  (HD + V_PAD)    // 132
#define P_STR  (BKV + P_PAD)   // 68

// floats of dynamic smem
#define SM_FLOATS (BQ*QK_STR /*Qs*/ + BKV*QK_STR /*Ks*/ + BKV*V_STR /*Vs*/ + BQ*P_STR /*Ps*/)
#define SM_BYTES  (SM_FLOATS * 4)

__global__ __launch_bounds__(256) void flash_attn_f32(
    const float* __restrict__ Q, const float* __restrict__ K,
    const float* __restrict__ V, float* __restrict__ O, float scale)
{
    extern __shared__ float sm[];
    float* Qs = sm;
    float* Ks = Qs + BQ * QK_STR;
    float* Vs = Ks + BKV * QK_STR;
    float* Ps = Vs + BKV * V_STR;

    const int tid = threadIdx.x;
    const int tx = tid & 15;
    const int ty = tid >> 4;

    const int q0 = blockIdx.x * BQ;
    const int bh = blockIdx.y;
    const int b = bh / HEADS, h = bh % HEADS;
    const size_t base = ((size_t)b * SEQ) * HID + (size_t)h * HD;

    // Load + pre-scale Q tile
    for (int idx = tid; idx < BQ * (HD / 4); idx += 256) {
        int r = idx / (HD / 4), c4 = idx % (HD / 4);
        float4 v = *reinterpret_cast<const float4*>(Q + base + (size_t)(q0 + r) * HID + c4 * 4);
        float* dst = &Qs[r * QK_STR + c4 * 4];
        dst[0] = v.x * scale; dst[1] = v.y * scale;
        dst[2] = v.z * scale; dst[3] = v.w * scale;
    }

    float m_i[4], l_i[4];
    #pragma unroll
    for (int i = 0; i < 4; ++i) { m_i[i] = -1e30f; l_i[i] = 0.0f; }
    float o_acc[4][8];
    #pragma unroll
    for (int i = 0; i < 4; ++i)
        #pragma unroll
        for (int j = 0; j < 8; ++j) o_acc[i][j] = 0.0f;

    for (int k0 = 0; k0 < SEQ; k0 += BKV) {
        __syncthreads();  // previous tile's P@V reads done before K/V overwrite

        for (int idx = tid; idx < BKV * (HD / 4); idx += 256) {
            int r = idx / (HD / 4), c4 = idx % (HD / 4);
            float4 kv = *reinterpret_cast<const float4*>(K + base + (size_t)(k0 + r) * HID + c4 * 4);
            float4 vv = *reinterpret_cast<const float4*>(V + base + (size_t)(k0 + r) * HID + c4 * 4);
            float* kd = &Ks[r * QK_STR + c4 * 4];
            kd[0] = kv.x; kd[1] = kv.y; kd[2] = kv.z; kd[3] = kv.w;
            *reinterpret_cast<float4*>(&Vs[r * V_STR + c4 * 4]) = vv;
        }
        __syncthreads();

        // scores 4x4 fragment
        float s[4][4];
        #pragma unroll
        for (int i = 0; i < 4; ++i)
            #pragma unroll
            for (int j = 0; j < 4; ++j) s[i][j] = 0.0f;

        for (int k = 0; k < HD; ++k) {
            float qf[4], kf[4];
            #pragma unroll
            for (int i = 0; i < 4; ++i) qf[i] = Qs[(ty * 4 + i) * QK_STR + k];
            #pragma unroll
            for (int j = 0; j < 4; ++j) kf[j] = Ks[(tx * 4 + j) * QK_STR + k];
            #pragma unroll
            for (int i = 0; i < 4; ++i)
                #pragma unroll
                for (int j = 0; j < 4; ++j)
                    s[i][j] += qf[i] * kf[j];
        }

        // online softmax per row (row r = ty*4+i spans the 16 tx lanes)
        #pragma unroll
        for (int i = 0; i < 4; ++i) {
            float mx = s[i][0];
            #pragma unroll
            for (int j = 1; j < 4; ++j) mx = fmaxf(mx, s[i][j]);
            #pragma unroll
            for (int off = 8; off >= 1; off >>= 1)
                mx = fmaxf(mx, __shfl_xor_sync(0xffffffffu, mx, off, 16));

            float m_new = fmaxf(m_i[i], mx);
            float corr = __expf(m_i[i] - m_new);
            float rs = 0.0f;
            #pragma unroll
            for (int j = 0; j < 4; ++j) {
                float p = __expf(s[i][j] - m_new);
                s[i][j] = p; rs += p;
            }
            #pragma unroll
            for (int off = 8; off >= 1; off >>= 1)
                rs += __shfl_xor_sync(0xffffffffu, rs, off, 16);

            l_i[i] = l_i[i] * corr + rs;
            m_i[i] = m_new;
            #pragma unroll
            for (int j = 0; j < 8; ++j) o_acc[i][j] *= corr;
            #pragma unroll
            for (int j = 0; j < 4; ++j)
                Ps[(ty * 4 + i) * P_STR + tx * 4 + j] = s[i][j];
        }
        __syncthreads();

        // O += P @ V ; thread owns rows ty*4+i, V cols tx*8..tx*8+7
        for (int jk = 0; jk < BKV; ++jk) {
            float pv[4];
            #pragma unroll
            for (int i = 0; i < 4; ++i) pv[i] = Ps[(ty * 4 + i) * P_STR + jk];
            float4 v0 = *reinterpret_cast<const float4*>(&Vs[jk * V_STR + tx * 8]);
            float4 v1 = *reinterpret_cast<const float4*>(&Vs[jk * V_STR + tx * 8 + 4]);
            #pragma unroll
            for (int i = 0; i < 4; ++i) {
                o_acc[i][0] += pv[i] * v0.x;
                o_acc[i][1] += pv[i] * v0.y;
                o_acc[i][2] += pv[i] * v0.z;
                o_acc[i][3] += pv[i] * v0.w;
                o_acc[i][4] += pv[i] * v1.x;
                o_acc[i][5] += pv[i] * v1.y;
                o_acc[i][6] += pv[i] * v1.z;
                o_acc[i][7] += pv[i] * v1.w;
            }
        }
    }

    // normalize + write out
    #pragma unroll
    for (int i = 0; i < 4; ++i) {
        float inv = 1.0f / l_i[i];
        size_t rbase = base + (size_t)(q0 + ty * 4 + i) * HID + tx * 8;
        float4 o0, o1;
        o0.x = o_acc[i][0] * inv; o0.y = o_acc[i][1] * inv;
        o0.z = o_acc[i][2] * inv; o0.w = o_acc[i][3] * inv;
        o1.x = o_acc[i][4] * inv; o1.y = o_acc[i][5] * inv;
        o1.z = o_acc[i][6] * inv; o1.w = o_acc[i][7] * inv;
        *reinterpret_cast<float4*>(O + rbase)     = o0;
        *reinterpret_cast<float4*>(O + rbase + 4) = o1;
    }
}

// ---------------------------------------------------------------------------
// Launch
// ---------------------------------------------------------------------------
extern "C" void kernel_launch(void* const* d_in, const int* in_sizes, int n_in,
                              void* d_out, int out_size)
{
    const float* x  = (const float*)d_in[0];
    const float* Wq = (const float*)d_in[1];
    const float* bq = (const float*)d_in[2];
    const float* Wk = (const float*)d_in[3];
    const float* bk = (const float*)d_in[4];
    const float* Wv = (const float*)d_in[5];
    const float* bv = (const float*)d_in[6];
    const float* Wo = (const float*)d_in[7];
    const float* bo = (const float*)d_in[8];
    float* out = (float*)d_out;

    float *Qb, *Kb, *Vb, *Ab;
    cudaGetSymbolAddress((void**)&Qb, g_Q);
    cudaGetSymbolAddress((void**)&Kb, g_K);
    cudaGetSymbolAddress((void**)&Vb, g_V);
    cudaGetSymbolAddress((void**)&Ab, g_A);

    dim3 ggrid(HID / BN, MROWS / BM);   // (16, 32)
    gemm_bias_nt<<<ggrid, 256>>>(x, Wq, bq, Qb, MROWS, HID, HID);
    gemm_bias_nt<<<ggrid, 256>>>(x, Wk, bk, Kb, MROWS, HID, HID);
    gemm_bias_nt<<<ggrid, 256>>>(x, Wv, bv, Vb, MROWS, HID, HID);

    static int smem_set = 0;
    if (!smem_set) {
        cudaFuncSetAttribute(flash_attn_f32,
                             cudaFuncAttributeMaxDynamicSharedMemorySize, SM_BYTES);
        smem_set = 1;
    }
    const float scale = 1.0f / sqrtf((float)HD);
    dim3 agrid(SEQ / BQ, BATCH * HEADS);  // (32, 32)
    flash_attn_f32<<<agrid, 256, SM_BYTES>>>(Qb, Kb, Vb, Ab, scale);

    gemm_bias_nt<<<ggrid, 256>>>(Ab, Wo, bo, out, MROWS, HID, HID);
}

// round 7
// speedup vs baseline: 1.4869x; 1.4869x over previous
#include <cuda_runtime.h>
#include <cuda_bf16.h>
#include <math.h>
#include <stdint.h>

// Problem constants
#define BATCH   2
#define SEQ     2048
#define HID     2048
#define HEADS   16
#define HD      128
#define MROWS   (BATCH * SEQ)          // 4096
#define MSZ     ((size_t)MROWS * HID)  // 8M elements
#define WSZ     ((size_t)HID * HID)    // 4M elements

// f32 scratch
__device__ float g_Q[MSZ];
__device__ float g_K[MSZ];
__device__ float g_V[MSZ];
__device__ float g_A[MSZ];
// bf16 hi/lo split scratch
__device__ __nv_bfloat16 g_xh[MSZ],  g_xl[MSZ];
__device__ __nv_bfloat16 g_ah[MSZ],  g_al[MSZ];
__device__ __nv_bfloat16 g_Wh[4][WSZ], g_Wl[4][WSZ];

// ===========================================================================
// Helpers
// ===========================================================================
__device__ __forceinline__ uint32_t smem_u32(const void* p) {
    uint32_t a;
    asm("{ .reg .u64 t; cvta.to.shared.u64 t, %1; cvt.u32.u64 %0, t; }"
        : "=r"(a) : "l"(p));
    return a;
}

#define CP_ASYNC16(dst, src) \
    asm volatile("cp.async.cg.shared.global [%0], [%1], 16;" \
        :: "r"(dst), "l"(src))
#define CP_COMMIT() asm volatile("cp.async.commit_group;" ::: "memory")
#define CP_WAIT1()  asm volatile("cp.async.wait_group 1;" ::: "memory")

#define LDMATRIX_X4(r0, r1, r2, r3, addr) \
    asm volatile("ldmatrix.sync.aligned.m8n8.x4.shared.b16 {%0,%1,%2,%3}, [%4];" \
        : "=r"(r0), "=r"(r1), "=r"(r2), "=r"(r3) : "r"(addr))

#define MMA_BF16(c, a, b0, b1) \
    asm volatile("mma.sync.aligned.m16n8k16.row.col.f32.bf16.bf16.f32 " \
        "{%0,%1,%2,%3}, {%4,%5,%6,%7}, {%8,%9}, {%0,%1,%2,%3};" \
        : "+f"((c)[0]), "+f"((c)[1]), "+f"((c)[2]), "+f"((c)[3]) \
        : "r"((a)[0]), "r"((a)[1]), "r"((a)[2]), "r"((a)[3]), "r"(b0), "r"(b1))

// ===========================================================================
// f32 -> bf16 hi/lo split (elementwise, memory bound)
// ===========================================================================
__global__ __launch_bounds__(256) void split_bf16_kernel(
    const float* __restrict__ src, __nv_bfloat16* __restrict__ hi,
    __nv_bfloat16* __restrict__ lo, int n4)
{
    int i = blockIdx.x * blockDim.x + threadIdx.x;
    if (i >= n4) return;
    float4 v = reinterpret_cast<const float4*>(src)[i];
    __nv_bfloat16 h0 = __float2bfloat16_rn(v.x);
    __nv_bfloat16 h1 = __float2bfloat16_rn(v.y);
    __nv_bfloat16 h2 = __float2bfloat16_rn(v.z);
    __nv_bfloat16 h3 = __float2bfloat16_rn(v.w);
    uint2 hv;
    hv.x = (uint32_t)__bfloat16_as_ushort(h0) | ((uint32_t)__bfloat16_as_ushort(h1) << 16);
    hv.y = (uint32_t)__bfloat16_as_ushort(h2) | ((uint32_t)__bfloat16_as_ushort(h3) << 16);
    reinterpret_cast<uint2*>(hi)[i] = hv;
    __nv_bfloat162 l01 = __floats2bfloat162_rn(v.x - __bfloat162float(h0),
                                               v.y - __bfloat162float(h1));
    __nv_bfloat162 l23 = __floats2bfloat162_rn(v.z - __bfloat162float(h2),
                                               v.w - __bfloat162float(h3));
    uint2 lv;
    lv.x = *reinterpret_cast<uint32_t*>(&l01);
    lv.y = *reinterpret_cast<uint32_t*>(&l23);
    reinterpret_cast<uint2*>(lo)[i] = lv;
}

// ===========================================================================
// Split-bf16 tensor-core GEMM via mma.sync:
//   C[M,N] = Ah@Wh^T + Ah@Wl^T + Al@Wh^T + bias     (A:[M,K], W:[N,K] bf16)
// CTA 128x128, K-chunk 64, 8 warps (2x4), warp tile 64x32.
// cp.async double-buffered SMEM, padded stride 72 bf16 (144B, conflict-free).
// ===========================================================================
#define GM 128
#define GN 128
#define KC 64
#define NCHUNK (HID / KC)     // 32
#define GSTR 72               // padded bf16 row stride
#define TELEM (128 * GSTR)    // elems per tile (9216)
#define STAGE_ELEM (4 * TELEM)
#define GEMM_SMEM_B (2 * STAGE_ELEM * 2)   // 147456 bytes

__global__ __launch_bounds__(256) void gemm_mma(
    const __nv_bfloat16* __restrict__ Ah, const __nv_bfloat16* __restrict__ Al,
    const __nv_bfloat16* __restrict__ Wh, const __nv_bfloat16* __restrict__ Wl,
    const float* __restrict__ bias, float* __restrict__ C,
    int M, int N, int K)
{
    extern __shared__ __nv_bfloat16 sm[];
    const int tid  = threadIdx.x;
    const int lane = tid & 31;
    const int wid  = tid >> 5;
    const int warp_m = wid >> 2;      // 0..1
    const int warp_n = wid & 3;       // 0..3
    const int m0 = blockIdx.y * GM;
    const int n0 = blockIdx.x * GN;

    const uint32_t smb = smem_u32(sm);

    float acc[4][4][4];
    #pragma unroll
    for (int a = 0; a < 4; ++a)
        #pragma unroll
        for (int b = 0; b < 4; ++b)
            #pragma unroll
            for (int c = 0; c < 4; ++c) acc[a][b][c] = 0.0f;

    // Per-thread load mapping: 4 (row,col16B) slots per tile.
    int lrow[4], lcol[4];
    #pragma unroll
    for (int i = 0; i < 4; ++i) {
        int linear = tid + i * 256;       // 0..1023
        lrow[i] = linear >> 3;            // 0..127
        lcol[i] = (linear & 7) * 8;       // bf16 col, 16B granules
    }

    // Issue cp.async loads of chunk ck into stage s
    auto load_chunk = [&](int ck, int s) {
        const int k0 = ck * KC;
        uint32_t stage_b = smb + (uint32_t)s * STAGE_ELEM * 2;
        const __nv_bfloat16* gsrc[4] = {
            Ah + (size_t)m0 * K + k0, Al + (size_t)m0 * K + k0,
            Wh + (size_t)n0 * K + k0, Wl + (size_t)n0 * K + k0 };
        #pragma unroll
        for (int t = 0; t < 4; ++t) {
            uint32_t tb = stage_b + (uint32_t)t * TELEM * 2;
            #pragma unroll
            for (int i = 0; i < 4; ++i) {
                uint32_t dst = tb + (uint32_t)(lrow[i] * GSTR + lcol[i]) * 2;
                const __nv_bfloat16* src = gsrc[t] + (size_t)lrow[i] * K + lcol[i];
                CP_ASYNC16(dst, src);
            }
        }
    };

    load_chunk(0, 0); CP_COMMIT();
    load_chunk(1, 1); CP_COMMIT();

    // ldmatrix lane address components
    const int arow  = warp_m * 64 + (lane & 15);
    const int aksel = (lane >> 4) << 3;                        // 0 or 8
    const int brow  = warp_n * 32 + ((lane >> 4) << 3) + (lane & 7);
    const int bksel = ((lane >> 3) & 1) * 8;                   // 0 or 8

    for (int ck = 0; ck < NCHUNK; ++ck) {
        const int s = ck & 1;
        CP_WAIT1();
        __syncthreads();

        uint32_t stage_b = smb + (uint32_t)s * STAGE_ELEM * 2;
        uint32_t bAh = stage_b;
        uint32_t bAl = stage_b + TELEM * 2;
        uint32_t bWh = stage_b + 2 * TELEM * 2;
        uint32_t bWl = stage_b + 3 * TELEM * 2;

        #pragma unroll
        for (int ks = 0; ks < KC / 16; ++ks) {
            const int akoff = ks * 16 + aksel;
            const int bkoff = ks * 16 + bksel;

            uint32_t ah[4][4], al[4][4];
            #pragma unroll
            for (int a = 0; a < 4; ++a) {
                uint32_t off = (uint32_t)((arow + a * 16) * GSTR + akoff) * 2;
                LDMATRIX_X4(ah[a][0], ah[a][1], ah[a][2], ah[a][3], bAh + off);
                LDMATRIX_X4(al[a][0], al[a][1], al[a][2], al[a][3], bAl + off);
            }
            uint32_t bh[2][4], bl[2][4];
            #pragma unroll
            for (int p = 0; p < 2; ++p) {
                uint32_t off = (uint32_t)((brow + p * 16) * GSTR + bkoff) * 2;
                LDMATRIX_X4(bh[p][0], bh[p][1], bh[p][2], bh[p][3], bWh + off);
                LDMATRIX_X4(bl[p][0], bl[p][1], bl[p][2], bl[p][3], bWl + off);
            }
            #pragma unroll
            for (int a = 0; a < 4; ++a)
                #pragma unroll
                for (int p = 0; p < 2; ++p)
                    #pragma unroll
                    for (int hq = 0; hq < 2; ++hq) {
                        int nb = p * 2 + hq;
                        MMA_BF16(acc[a][nb], ah[a], bh[p][hq*2], bh[p][hq*2+1]);
                        MMA_BF16(acc[a][nb], ah[a], bl[p][hq*2], bl[p][hq*2+1]);
                        MMA_BF16(acc[a][nb], al[a], bh[p][hq*2], bh[p][hq*2+1]);
                    }
        }
        __syncthreads();
        if (ck + 2 < NCHUNK) load_chunk(ck + 2, s);
        CP_COMMIT();   // empty group OK at the tail; keeps wait_group 1 sound
    }

    // Epilogue: C-fragment rows (t/4, t/4+8), cols (t%4)*2..+1
    #pragma unroll
    for (int a = 0; a < 4; ++a) {
        int r_lo = m0 + warp_m * 64 + a * 16 + (lane >> 2);
        #pragma unroll
        for (int nb = 0; nb < 4; ++nb) {
            int c = n0 + warp_n * 32 + nb * 8 + (lane & 3) * 2;
            float2 blo = { bias[c], bias[c + 1] };
            float2 v0 = { acc[a][nb][0] + blo.x, acc[a][nb][1] + blo.y };
            float2 v1 = { acc[a][nb][2] + blo.x, acc[a][nb][3] + blo.y };
            *reinterpret_cast<float2*>(C + (size_t)r_lo * N + c) = v0;
            *reinterpret_cast<float2*>(C + (size_t)(r_lo + 8) * N + c) = v1;
        }
    }
}

// ---------------------------------------------------------------------------
// Flash attention (fp32, no mask) — unchanged from passing R4 kernel.
// ---------------------------------------------------------------------------
#define BQ  64
#define BKV 64
#define QK_PAD 1
#define V_PAD  4
#define P_PAD  4

#define QK_STR (HD + QK_PAD)   // 129
#define V_STR  (HD + V_PAD)    // 132
#define P_STR  (BKV + P_PAD)   // 68

#define SM_FLOATS (BQ*QK_STR + BKV*QK_STR + BKV*V_STR + BQ*P_STR)
#define SM_BYTES  (SM_FLOATS * 4)

__global__ __launch_bounds__(256) void flash_attn_f32(
    const float* __restrict__ Q, const float* __restrict__ K,
    const float* __restrict__ V, float* __restrict__ O, float scale)
{
    extern __shared__ float smf[];
    float* Qs = smf;
    float* Ks = Qs + BQ * QK_STR;
    float* Vs = Ks + BKV * QK_STR;
    float* Ps = Vs + BKV * V_STR;

    const int tid = threadIdx.x;
    const int tx = tid & 15;
    const int ty = tid >> 4;

    const int q0 = blockIdx.x * BQ;
    const int bh = blockIdx.y;
    const int b = bh / HEADS, h = bh % HEADS;
    const size_t base = ((size_t)b * SEQ) * HID + (size_t)h * HD;

    for (int idx = tid; idx < BQ * (HD / 4); idx += 256) {
        int r = idx / (HD / 4), c4 = idx % (HD / 4);
        float4 v = *reinterpret_cast<const float4*>(Q + base + (size_t)(q0 + r) * HID + c4 * 4);
        float* dst = &Qs[r * QK_STR + c4 * 4];
        dst[0] = v.x * scale; dst[1] = v.y * scale;
        dst[2] = v.z * scale; dst[3] = v.w * scale;
    }

    float m_i[4], l_i[4];
    #pragma unroll
    for (int i = 0; i < 4; ++i) { m_i[i] = -1e30f; l_i[i] = 0.0f; }
    float o_acc[4][8];
    #pragma unroll
    for (int i = 0; i < 4; ++i)
        #pragma unroll
        for (int j = 0; j < 8; ++j) o_acc[i][j] = 0.0f;

    for (int k0 = 0; k0 < SEQ; k0 += BKV) {
        __syncthreads();

        for (int idx = tid; idx < BKV * (HD / 4); idx += 256) {
            int r = idx / (HD / 4), c4 = idx % (HD / 4);
            float4 kv = *reinterpret_cast<const float4*>(K + base + (size_t)(k0 + r) * HID + c4 * 4);
            float4 vv = *reinterpret_cast<const float4*>(V + base + (size_t)(k0 + r) * HID + c4 * 4);
            float* kd = &Ks[r * QK_STR + c4 * 4];
            kd[0] = kv.x; kd[1] = kv.y; kd[2] = kv.z; kd[3] = kv.w;
            *reinterpret_cast<float4*>(&Vs[r * V_STR + c4 * 4]) = vv;
        }
        __syncthreads();

        float s[4][4];
        #pragma unroll
        for (int i = 0; i < 4; ++i)
            #pragma unroll
            for (int j = 0; j < 4; ++j) s[i][j] = 0.0f;

        for (int k = 0; k < HD; ++k) {
            float qf[4], kf[4];
            #pragma unroll
            for (int i = 0; i < 4; ++i) qf[i] = Qs[(ty * 4 + i) * QK_STR + k];
            #pragma unroll
            for (int j = 0; j < 4; ++j) kf[j] = Ks[(tx * 4 + j) * QK_STR + k];
            #pragma unroll
            for (int i = 0; i < 4; ++i)
                #pragma unroll
                for (int j = 0; j < 4; ++j)
                    s[i][j] += qf[i] * kf[j];
        }

        #pragma unroll
        for (int i = 0; i < 4; ++i) {
            float mx = s[i][0];
            #pragma unroll
            for (int j = 1; j < 4; ++j) mx = fmaxf(mx, s[i][j]);
            #pragma unroll
            for (int off = 8; off >= 1; off >>= 1)
                mx = fmaxf(mx, __shfl_xor_sync(0xffffffffu, mx, off, 16));

            float m_new = fmaxf(m_i[i], mx);
            float corr = __expf(m_i[i] - m_new);
            float rs = 0.0f;
            #pragma unroll
            for (int j = 0; j < 4; ++j) {
                float p = __expf(s[i][j] - m_new);
                s[i][j] = p; rs += p;
            }
            #pragma unroll
            for (int off = 8; off >= 1; off >>= 1)
                rs += __shfl_xor_sync(0xffffffffu, rs, off, 16);

            l_i[i] = l_i[i] * corr + rs;
            m_i[i] = m_new;
            #pragma unroll
            for (int j = 0; j < 8; ++j) o_acc[i][j] *= corr;
            #pragma unroll
            for (int j = 0; j < 4; ++j)
                Ps[(ty * 4 + i) * P_STR + tx * 4 + j] = s[i][j];
        }
        __syncthreads();

        for (int jk = 0; jk < BKV; ++jk) {
            float pv[4];
            #pragma unroll
            for (int i = 0; i < 4; ++i) pv[i] = Ps[(ty * 4 + i) * P_STR + jk];
            float4 v0 = *reinterpret_cast<const float4*>(&Vs[jk * V_STR + tx * 8]);
            float4 v1 = *reinterpret_cast<const float4*>(&Vs[jk * V_STR + tx * 8 + 4]);
            #pragma unroll
            for (int i = 0; i < 4; ++i) {
                o_acc[i][0] += pv[i] * v0.x;
                o_acc[i][1] += pv[i] * v0.y;
                o_acc[i][2] += pv[i] * v0.z;
                o_acc[i][3] += pv[i] * v0.w;
                o_acc[i][4] += pv[i] * v1.x;
                o_acc[i][5] += pv[i] * v1.y;
                o_acc[i][6] += pv[i] * v1.z;
                o_acc[i][7] += pv[i] * v1.w;
            }
        }
    }

    #pragma unroll
    for (int i = 0; i < 4; ++i) {
        float inv = 1.0f / l_i[i];
        size_t rbase = base + (size_t)(q0 + ty * 4 + i) * HID + tx * 8;
        float4 o0, o1;
        o0.x = o_acc[i][0] * inv; o0.y = o_acc[i][1] * inv;
        o0.z = o_acc[i][2] * inv; o0.w = o_acc[i][3] * inv;
        o1.x = o_acc[i][4] * inv; o1.y = o_acc[i][5] * inv;
        o1.z = o_acc[i][6] * inv; o1.w = o_acc[i][7] * inv;
        *reinterpret_cast<float4*>(O + rbase)     = o0;
        *reinterpret_cast<float4*>(O + rbase + 4) = o1;
    }
}

// ---------------------------------------------------------------------------
// Launch
// ---------------------------------------------------------------------------
extern "C" void kernel_launch(void* const* d_in, const int* in_sizes, int n_in,
                              void* d_out, int out_size)
{
    const float* x  = (const float*)d_in[0];
    const float* Wq = (const float*)d_in[1];
    const float* bq = (const float*)d_in[2];
    const float* Wk = (const float*)d_in[3];
    const float* bk = (const float*)d_in[4];
    const float* Wv = (const float*)d_in[5];
    const float* bv = (const float*)d_in[6];
    const float* Wo = (const float*)d_in[7];
    const float* bo = (const float*)d_in[8];
    float* out = (float*)d_out;

    float *Qb, *Kb, *Vb, *Ab;
    cudaGetSymbolAddress((void**)&Qb, g_Q);
    cudaGetSymbolAddress((void**)&Kb, g_K);
    cudaGetSymbolAddress((void**)&Vb, g_V);
    cudaGetSymbolAddress((void**)&Ab, g_A);
    __nv_bfloat16 *xh, *xl, *ah, *al, *Whb, *Wlb;
    cudaGetSymbolAddress((void**)&xh, g_xh);
    cudaGetSymbolAddress((void**)&xl, g_xl);
    cudaGetSymbolAddress((void**)&ah, g_ah);
    cudaGetSymbolAddress((void**)&al, g_al);
    cudaGetSymbolAddress((void**)&Whb, g_Wh);
    cudaGetSymbolAddress((void**)&Wlb, g_Wl);

    static int attr_set = 0;
    if (!attr_set) {
        cudaFuncSetAttribute(gemm_mma,
                             cudaFuncAttributeMaxDynamicSharedMemorySize, GEMM_SMEM_B);
        cudaFuncSetAttribute(flash_attn_f32,
                             cudaFuncAttributeMaxDynamicSharedMemorySize, SM_BYTES);
        attr_set = 1;
    }

    // Split conversions
    const int n4x = (int)(MSZ / 4), n4w = (int)(WSZ / 4);
    split_bf16_kernel<<<(n4x + 255) / 256, 256>>>(x, xh, xl, n4x);
    const float* Ws[4] = { Wq, Wk, Wv, Wo };
    for (int i = 0; i < 4; ++i)
        split_bf16_kernel<<<(n4w + 255) / 256, 256>>>(
            Ws[i], Whb + (size_t)i * WSZ, Wlb + (size_t)i * WSZ, n4w);

    dim3 ggrid(HID / GN, MROWS / GM);   // (16, 32)
    gemm_mma<<<ggrid, 256, GEMM_SMEM_B>>>(xh, xl, Whb + 0 * WSZ, Wlb + 0 * WSZ, bq, Qb, MROWS, HID, HID);
    gemm_mma<<<ggrid, 256, GEMM_SMEM_B>>>(xh, xl, Whb + 1 * WSZ, Wlb + 1 * WSZ, bk, Kb, MROWS, HID, HID);
    gemm_mma<<<ggrid, 256, GEMM_SMEM_B>>>(xh, xl, Whb + 2 * WSZ, Wlb + 2 * WSZ, bv, Vb, MROWS, HID, HID);

    const float scale = 1.0f / sqrtf((float)HD);
    dim3 agrid(SEQ / BQ, BATCH * HEADS);  // (32, 32)
    flash_attn_f32<<<agrid, 256, SM_BYTES>>>(Qb, Kb, Vb, Ab, scale);

    split_bf16_kernel<<<(n4x + 255) / 256, 256>>>(Ab, ah, al, n4x);
    gemm_mma<<<ggrid, 256, GEMM_SMEM_B>>>(ah, al, Whb + 3 * WSZ, Wlb + 3 * WSZ, bo, out, MROWS, HID, HID);
}